// round 9
// baseline (speedup 1.0000x reference)
#include <cuda_runtime.h>
#include <cstdint>

// Scratch: pre[row][32], row = b*512 + t, col = gate*8 + qubit. 33.5 MB.
__device__ float g_pre[512 * 512 * 32];
// Ready flags: [tc*256 + b2] -> gemm chunk (batches 2*b2, 2*b2+1; t-half tc) done.
__device__ int g_flag[512];

// ---------------------------------------------------------------------------
__device__ __forceinline__ unsigned long long ffma2(unsigned long long a,
                                                    unsigned long long b,
                                                    unsigned long long c) {
    unsigned long long d;
    asm("fma.rn.f32x2 %0, %1, %2, %3;" : "=l"(d) : "l"(a), "l"(b), "l"(c));
    return d;
}
__device__ __forceinline__ float ex2_approx(float x) {
    float y; asm("ex2.approx.f32 %0, %1;" : "=f"(y) : "f"(x)); return y;
}
__device__ __forceinline__ float rcp_approx(float x) {
    float y; asm("rcp.approx.f32 %0, %1;" : "=f"(y) : "f"(x)); return y;
}
__device__ __forceinline__ void set_flag(int* p) {
    asm volatile("st.global.release.gpu.b32 [%0], %1;" :: "l"(p), "r"(1) : "memory");
}
__device__ __forceinline__ void wait_flag(const int* p) {
    int v;
    while (true) {
        asm volatile("ld.global.acquire.gpu.b32 %0, [%1];" : "=r"(v) : "l"(p) : "memory");
        if (v) break;
        __nanosleep(64);
    }
}

__global__ void zero_flags_kernel() {
    g_flag[threadIdx.x] = 0;
}

// ---------------------------------------------------------------------------
// Fused kernel.
//  Blocks 0..511   : GEMM. Block g -> tc = g>>8 (t-half), b2 = g&255 (batch pair).
//                    Covers 512 rows: batches 2*b2, 2*b2+1, t in [tc*256, tc*256+256).
//                    Thread: 4 row-pairs x 8 cols, f32x2-packed (FMA-pipe bound).
//  Blocks 512..575 : recurrence. 8 warps/block, warp = one batch element,
//                    lane = gate*8 + qubit. Spin on flags, pipelined behind GEMM.
// ---------------------------------------------------------------------------
constexpr int KT   = 8;      // k-tile
constexpr int XS   = 514;    // smem X row stride (floats), 512 rows + pad
constexpr int SMEM_FLOATS = 16384 + 2 * KT * XS;  // W pairs + double-buffered X

__global__ void __launch_bounds__(256, 2) fused_kernel(
    const float* __restrict__ X,
    const float* __restrict__ Wf, const float* __restrict__ bf,
    const float* __restrict__ Wi, const float* __restrict__ bi,
    const float* __restrict__ Wg, const float* __restrict__ bg,
    const float* __restrict__ Wo, const float* __restrict__ bo,
    const float* __restrict__ th,
    float* __restrict__ out)
{
    const int tid = threadIdx.x;

    if (blockIdx.x < 512) {
        // =================== GEMM role ===================
        extern __shared__ float sm[];
        float2* sW2 = reinterpret_cast<float2*>(sm);   // [256][32] dup pairs, 64 KB
        float*  sX  = sm + 16384;                      // [2][KT][XS]

        const int tc = blockIdx.x >> 8;
        const int b2 = blockIdx.x & 255;

        // Stage W as duplicated (w,w) pairs (W row stride 264, first 256 = input).
#pragma unroll
        for (int gi = 0; gi < 4; gi++) {
            const float* Wp = (gi == 0) ? Wf : (gi == 1) ? Wi : (gi == 2) ? Wg : Wo;
            for (int idx = tid; idx < 2048; idx += 256) {
                int k = idx >> 3, nn = idx & 7;
                float w = Wp[nn * 264 + k];
                sW2[k * 32 + gi * 8 + nn] = make_float2(w, w);
            }
        }

        // virtual row v (0..511) -> physical row base0 + (v>>8)*512 + (v&255)
        const size_t base0 = (size_t)(2 * b2) * 512 + tc * 256;

        const int cg = tid >> 6;     // gate (col group), uniform per warp
        const int rp = tid & 63;     // row-pair id
        const int k4 = tid & 1;      // staging k chunk (4 floats)
        const int rq = tid >> 1;     // staging row base (0..127)

        size_t srow[4];
#pragma unroll
        for (int i = 0; i < 4; i++) {
            int v = rq + 128 * i;
            srow[i] = base0 + (size_t)(v >> 8) * 512 + (v & 255);
        }

        float4 ldv[4];
#pragma unroll
        for (int i = 0; i < 4; i++)
            ldv[i] = *reinterpret_cast<const float4*>(X + srow[i] * 256 + k4 * 4);

        unsigned long long acc[4][8];
#pragma unroll
        for (int j = 0; j < 4; j++)
#pragma unroll
            for (int c = 0; c < 8; c++) acc[j][c] = 0ull;

        // store tile 0 into buffer 0 (first sync also covers sW2)
#pragma unroll
        for (int i = 0; i < 4; i++) {
            float* dst = sX + k4 * 4 * XS + rq + 128 * i;
            dst[0 * XS] = ldv[i].x; dst[1 * XS] = ldv[i].y;
            dst[2 * XS] = ldv[i].z; dst[3 * XS] = ldv[i].w;
        }

        for (int kt = 0; kt < 32; kt++) {
            __syncthreads();
            if (kt < 31) {
#pragma unroll
                for (int i = 0; i < 4; i++)
                    ldv[i] = *reinterpret_cast<const float4*>(
                        X + srow[i] * 256 + (kt + 1) * KT + k4 * 4);
            }
            const float*  bx = sX + (kt & 1) * (KT * XS);
            const float2* wk = sW2 + (size_t)kt * KT * 32 + cg * 8;
#pragma unroll
            for (int kk = 0; kk < KT; kk++) {
                unsigned long long xp[4];
#pragma unroll
                for (int j = 0; j < 4; j++)
                    xp[j] = *reinterpret_cast<const unsigned long long*>(
                        bx + kk * XS + 2 * rp + 128 * j);
                const ulonglong2* w2 = reinterpret_cast<const ulonglong2*>(wk + kk * 32);
                ulonglong2 wa = w2[0], wb = w2[1], wc = w2[2], wd = w2[3];
#pragma unroll
                for (int j = 0; j < 4; j++) {
                    acc[j][0] = ffma2(wa.x, xp[j], acc[j][0]);
                    acc[j][1] = ffma2(wa.y, xp[j], acc[j][1]);
                    acc[j][2] = ffma2(wb.x, xp[j], acc[j][2]);
                    acc[j][3] = ffma2(wb.y, xp[j], acc[j][3]);
                    acc[j][4] = ffma2(wc.x, xp[j], acc[j][4]);
                    acc[j][5] = ffma2(wc.y, xp[j], acc[j][5]);
                    acc[j][6] = ffma2(wd.x, xp[j], acc[j][6]);
                    acc[j][7] = ffma2(wd.y, xp[j], acc[j][7]);
                }
            }
            if (kt < 31) {
                float* dstb = sX + ((kt + 1) & 1) * (KT * XS);
#pragma unroll
                for (int i = 0; i < 4; i++) {
                    float* dst = dstb + k4 * 4 * XS + rq + 128 * i;
                    dst[0 * XS] = ldv[i].x; dst[1 * XS] = ldv[i].y;
                    dst[2 * XS] = ldv[i].z; dst[3 * XS] = ldv[i].w;
                }
            }
        }

        // Epilogue: + bias + theta, write 4 row-pairs x 8 cols.
        const float* bptr = (cg == 0) ? bf : (cg == 1) ? bi : (cg == 2) ? bg : bo;
        float bt[8];
#pragma unroll
        for (int c = 0; c < 8; c++) bt[c] = bptr[c] + th[cg * 8 + c];
#pragma unroll
        for (int j = 0; j < 4; j++) {
            int v0 = 2 * rp + 128 * j;
            size_t pr = base0 + (size_t)(v0 >> 8) * 512 + (v0 & 255);
            float o0[8], o1[8];
#pragma unroll
            for (int c = 0; c < 8; c++) {
                float2 av = *reinterpret_cast<float2*>(&acc[j][c]);
                o0[c] = av.x + bt[c];
                o1[c] = av.y + bt[c];
            }
            float4* p0 = reinterpret_cast<float4*>(g_pre + pr * 32 + cg * 8);
            float4* p1 = reinterpret_cast<float4*>(g_pre + (pr + 1) * 32 + cg * 8);
            p0[0] = make_float4(o0[0], o0[1], o0[2], o0[3]);
            p0[1] = make_float4(o0[4], o0[5], o0[6], o0[7]);
            p1[0] = make_float4(o1[0], o1[1], o1[2], o1[3]);
            p1[1] = make_float4(o1[4], o1[5], o1[6], o1[7]);
        }

        __syncthreads();
        if (tid == 0) {
            __threadfence();
            set_flag(&g_flag[tc * 256 + b2]);
        }
        return;
    }

    // =================== Recurrence role ===================
    // 8 warps per block, one batch per warp; lane = gate*8 + qubit.
    //   m_k = prod_{j<=k} cos(ang_j) (k>=1),  m_0 = prod_{j=1..7} cos(ang_j)
    const int wid  = tid >> 5;
    const int lane = tid & 31;
    const int b    = (blockIdx.x - 512) * 8 + wid;
    const int g    = lane >> 3;
    const int n    = lane & 7;
    const int segb = g * 8;
    const unsigned FULL = 0xffffffffu;
    const float L2E = 1.4426950408889634f;

    const float* Wsel = (g == 0) ? Wf : (g == 1) ? Wi : (g == 2) ? Wg : Wo;
    float wh[8];
#pragma unroll
    for (int h = 0; h < 8; h++) wh[h] = Wsel[n * 264 + 256 + h];

    float incm[8];
#pragma unroll
    for (int j = 0; j < 8; j++)
        incm[j] = ((n == 0) ? (j >= 1) : (j <= n)) ? 1.0f : 0.0f;

    const float sA2 = (g == 2) ? (-2.0f * L2E) : (-L2E);
    const float am  = (g == 2) ? 2.0f : 1.0f;
    const float ab  = (g == 2) ? -1.0f : 0.0f;

    float hxa[8];
#pragma unroll
    for (int h = 0; h < 8; h++) hxa[h] = 0.f;
    float cx = 0.f, hx = 0.f;

    const float* pb = g_pre + (size_t)b * 512 * 32 + lane;
    float* ob = out + (size_t)b * 512 * 8 + n;

    const int fb = b >> 1;
    wait_flag(&g_flag[fb]);                 // t-half 0 ready

    float p0 = __ldg(pb);
    float p1 = __ldg(pb + 32);
    for (int t = 0; t < 512; t++) {
        if (t == 254) wait_flag(&g_flag[256 + fb]);   // t-half 1 before prefetch
        float p2 = __ldg(pb + ((t + 2) & 511) * 32);

        // angle = pre + W_h . hx
        float s1 = p0, s2 = 0.f;
        s1 = fmaf(wh[0], hxa[0], s1);  s2 = fmaf(wh[1], hxa[1], s2);
        s1 = fmaf(wh[2], hxa[2], s1);  s2 = fmaf(wh[3], hxa[3], s2);
        s1 = fmaf(wh[4], hxa[4], s1);  s2 = fmaf(wh[5], hxa[5], s2);
        s1 = fmaf(wh[6], hxa[6], s1);  s2 = fmaf(wh[7], hxa[7], s2);
        float ang = s1 + s2;

        float cm1 = __cosf(ang) - 1.0f;

        // Broadcast (cos-1) of this gate's 8 qubits; masked tree product.
        float vv[8];
#pragma unroll
        for (int j = 0; j < 8; j++) {
            float cj = __shfl_sync(FULL, cm1, segb + j);
            vv[j] = fmaf(incm[j], cj, 1.0f);
        }
        float m = ((vv[0] * vv[1]) * (vv[2] * vv[3])) *
                  ((vv[4] * vv[5]) * (vv[6] * vv[7]));

        // a = am * sigmoid(scale*m) + ab
        float e = ex2_approx(m * sA2);
        float r = rcp_approx(1.0f + e);
        float a = fmaf(am, r, ab);

        float fv = __shfl_sync(FULL, a, n);
        float iv = __shfl_sync(FULL, a, n + 8);
        float gv = __shfl_sync(FULL, a, n + 16);
        float ov = __shfl_sync(FULL, a, n + 24);

        cx = fmaf(fv, cx, iv * gv);

        float e2 = ex2_approx(cx * (-2.0f * L2E));
        float r2 = rcp_approx(1.0f + e2);
        hx = ov * fmaf(2.0f, r2, -1.0f);

#pragma unroll
        for (int h = 0; h < 8; h++) hxa[h] = __shfl_sync(FULL, hx, h);

        if (lane < 8) ob[t * 8] = hx;
        p0 = p1; p1 = p2;
    }

    if (lane < 8) {
        out[2097152 + b * 8 + n] = hx;          // final hx
        out[2097152 + 4096 + b * 8 + n] = cx;   // final cx
    }
}

// ---------------------------------------------------------------------------
extern "C" void kernel_launch(void* const* d_in, const int* in_sizes, int n_in,
                              void* d_out, int out_size) {
    const float* X  = (const float*)d_in[0];
    const float* Wf = (const float*)d_in[1];
    const float* bf = (const float*)d_in[2];
    const float* Wi = (const float*)d_in[3];
    const float* bi = (const float*)d_in[4];
    const float* Wg = (const float*)d_in[5];
    const float* bg = (const float*)d_in[6];
    const float* Wo = (const float*)d_in[7];
    const float* bo = (const float*)d_in[8];
    const float* th = (const float*)d_in[9];
    float* out = (float*)d_out;

    const int smem = SMEM_FLOATS * 4;   // 98432 B
    cudaFuncSetAttribute(fused_kernel,
                         cudaFuncAttributeMaxDynamicSharedMemorySize, smem);

    zero_flags_kernel<<<1, 512>>>();
    fused_kernel<<<576, 256, smem>>>(X, Wf, bf, Wi, bi, Wg, bg, Wo, bo, th, out);
}

// round 11
// speedup vs baseline: 1.0689x; 1.0689x over previous
#include <cuda_runtime.h>
#include <cstdint>

// Scratch: pre[row][32], row = b*512 + t, col = gate*8 + qubit. 33.5 MB.
__device__ float g_pre[512 * 512 * 32];

// ---------------------------------------------------------------------------
__device__ __forceinline__ unsigned long long ffma2(unsigned long long a,
                                                    unsigned long long b,
                                                    unsigned long long c) {
    unsigned long long d;
    asm("fma.rn.f32x2 %0, %1, %2, %3;" : "=l"(d) : "l"(a), "l"(b), "l"(c));
    return d;
}
__device__ __forceinline__ float ex2_approx(float x) {
    float y; asm("ex2.approx.f32 %0, %1;" : "=f"(y) : "f"(x)); return y;
}
__device__ __forceinline__ float rcp_approx(float x) {
    float y; asm("rcp.approx.f32 %0, %1;" : "=f"(y) : "f"(x)); return y;
}

// ---------------------------------------------------------------------------
// Kernel 1: pre[r][c] = sum_k X[r][k]*W[c][k] + bias[c] + theta[c]
//   M=262144 rows, K=256, N=32. Block: 256 threads, 512 rows x 32 cols.
//   Thread: 4 row-pairs x 8 cols, f32x2-packed -> 32 FFMA2 / 12 LDS per kk.
// ---------------------------------------------------------------------------
constexpr int KT = 8;      // k-tile
constexpr int XS = 514;    // smem X row stride (floats): 512 rows + pad
constexpr int SMEM_FLOATS = 16384 + 2 * KT * XS;   // W pairs + dbl-buffered X

__global__ void __launch_bounds__(256, 2) gemm_kernel(
    const float* __restrict__ X,
    const float* __restrict__ Wf, const float* __restrict__ bf,
    const float* __restrict__ Wi, const float* __restrict__ bi,
    const float* __restrict__ Wg, const float* __restrict__ bg,
    const float* __restrict__ Wo, const float* __restrict__ bo,
    const float* __restrict__ th)
{
    extern __shared__ float sm[];
    float2* sW2 = reinterpret_cast<float2*>(sm);   // [256][32] dup (w,w) pairs, 64 KB
    float*  sX  = sm + 16384;                      // [2][KT][XS]

    const int tid = threadIdx.x;

    // Stage W as duplicated (w,w) pairs (W row stride 264; first 256 = input part).
#pragma unroll
    for (int gi = 0; gi < 4; gi++) {
        const float* Wp = (gi == 0) ? Wf : (gi == 1) ? Wi : (gi == 2) ? Wg : Wo;
        for (int idx = tid; idx < 2048; idx += 256) {
            int k = idx >> 3, nn = idx & 7;
            float w = Wp[nn * 264 + k];
            sW2[k * 32 + gi * 8 + nn] = make_float2(w, w);
        }
    }

    const size_t base0 = (size_t)blockIdx.x * 512;

    const int cg = tid >> 6;     // gate (col group), uniform per warp
    const int rp = tid & 63;     // row-pair id (rows 2rp,2rp+1, +128j)
    const int k4 = tid & 1;      // staging k chunk (4 floats)
    const int rq = tid >> 1;     // staging row base (0..127)

    float4 ldv[4];
#pragma unroll
    for (int i = 0; i < 4; i++)
        ldv[i] = *reinterpret_cast<const float4*>(
            X + (base0 + rq + 128 * i) * 256 + k4 * 4);

    unsigned long long acc[4][8];
#pragma unroll
    for (int j = 0; j < 4; j++)
#pragma unroll
        for (int c = 0; c < 8; c++) acc[j][c] = 0ull;

    // store tile 0 into buffer 0 (first sync also covers sW2)
#pragma unroll
    for (int i = 0; i < 4; i++) {
        float* dst = sX + k4 * 4 * XS + rq + 128 * i;
        dst[0 * XS] = ldv[i].x; dst[1 * XS] = ldv[i].y;
        dst[2 * XS] = ldv[i].z; dst[3 * XS] = ldv[i].w;
    }

    for (int kt = 0; kt < 32; kt++) {
        __syncthreads();
        if (kt < 31) {
#pragma unroll
            for (int i = 0; i < 4; i++)
                ldv[i] = *reinterpret_cast<const float4*>(
                    X + (base0 + rq + 128 * i) * 256 + (kt + 1) * KT + k4 * 4);
        }
        const float*  bx = sX + (kt & 1) * (KT * XS);
        const float2* wk = sW2 + (size_t)kt * KT * 32 + cg * 8;
#pragma unroll
        for (int kk = 0; kk < KT; kk++) {
            unsigned long long xp[4];
#pragma unroll
            for (int j = 0; j < 4; j++)
                xp[j] = *reinterpret_cast<const unsigned long long*>(
                    bx + kk * XS + 2 * rp + 128 * j);
            const ulonglong2* w2 = reinterpret_cast<const ulonglong2*>(wk + kk * 32);
            ulonglong2 wa = w2[0], wb = w2[1], wc = w2[2], wd = w2[3];
#pragma unroll
            for (int j = 0; j < 4; j++) {
                acc[j][0] = ffma2(wa.x, xp[j], acc[j][0]);
                acc[j][1] = ffma2(wa.y, xp[j], acc[j][1]);
                acc[j][2] = ffma2(wb.x, xp[j], acc[j][2]);
                acc[j][3] = ffma2(wb.y, xp[j], acc[j][3]);
                acc[j][4] = ffma2(wc.x, xp[j], acc[j][4]);
                acc[j][5] = ffma2(wc.y, xp[j], acc[j][5]);
                acc[j][6] = ffma2(wd.x, xp[j], acc[j][6]);
                acc[j][7] = ffma2(wd.y, xp[j], acc[j][7]);
            }
        }
        if (kt < 31) {
            float* dstb = sX + ((kt + 1) & 1) * (KT * XS);
#pragma unroll
            for (int i = 0; i < 4; i++) {
                float* dst = dstb + k4 * 4 * XS + rq + 128 * i;
                dst[0 * XS] = ldv[i].x; dst[1 * XS] = ldv[i].y;
                dst[2 * XS] = ldv[i].z; dst[3 * XS] = ldv[i].w;
            }
        }
    }

    // Epilogue: + bias + theta, write 4 row-pairs x 8 cols.
    const float* bptr = (cg == 0) ? bf : (cg == 1) ? bi : (cg == 2) ? bg : bo;
    float bt[8];
#pragma unroll
    for (int c = 0; c < 8; c++) bt[c] = bptr[c] + th[cg * 8 + c];
#pragma unroll
    for (int j = 0; j < 4; j++) {
        size_t pr = base0 + 2 * rp + 128 * j;
        float o0[8], o1[8];
#pragma unroll
        for (int c = 0; c < 8; c++) {
            float2 av = *reinterpret_cast<float2*>(&acc[j][c]);
            o0[c] = av.x + bt[c];
            o1[c] = av.y + bt[c];
        }
        float4* p0 = reinterpret_cast<float4*>(g_pre + pr * 32 + cg * 8);
        float4* p1 = reinterpret_cast<float4*>(g_pre + (pr + 1) * 32 + cg * 8);
        p0[0] = make_float4(o0[0], o0[1], o0[2], o0[3]);
        p0[1] = make_float4(o0[4], o0[5], o0[6], o0[7]);
        p1[0] = make_float4(o1[0], o1[1], o1[2], o1[3]);
        p1[1] = make_float4(o1[4], o1[5], o1[6], o1[7]);
    }
}

// ---------------------------------------------------------------------------
// Kernel 2: LSTM recurrence. 4 warps/block (one per SMSP), one batch per warp,
// lane = gate*8 + qubit. 128 blocks -> <=1 block/SM -> 1 warp/SMSP: the step
// time is the pure dependency chain, no scheduler contention.
//   m_k = prod_{j<=k} cos(ang_j) (k>=1),  m_0 = prod_{j=1..7} cos(ang_j)
// ---------------------------------------------------------------------------
__global__ void __launch_bounds__(128) recur_kernel(
    const float* __restrict__ Wf, const float* __restrict__ Wi,
    const float* __restrict__ Wg, const float* __restrict__ Wo,
    float* __restrict__ out)
{
    const int wid  = threadIdx.x >> 5;
    const int lane = threadIdx.x & 31;
    const int b    = blockIdx.x * 4 + wid;
    const int g    = lane >> 3;
    const int n    = lane & 7;
    const int segb = g * 8;
    const unsigned FULL = 0xffffffffu;
    const float L2E = 1.4426950408889634f;

    const float* Wsel = (g == 0) ? Wf : (g == 1) ? Wi : (g == 2) ? Wg : Wo;
    float wh[8];
#pragma unroll
    for (int h = 0; h < 8; h++) wh[h] = Wsel[n * 264 + 256 + h];

    // Product inclusion mask: n==0 -> j in 1..7, else j in 0..n.
    float incm[8];
#pragma unroll
    for (int j = 0; j < 8; j++)
        incm[j] = ((n == 0) ? (j >= 1) : (j <= n)) ? 1.0f : 0.0f;

    // Activation: f,i,o -> sigmoid(m); g -> tanh(m) = 2*sigmoid(2m)-1.
    const float sA2 = (g == 2) ? (-2.0f * L2E) : (-L2E);
    const float am  = (g == 2) ? 2.0f : 1.0f;
    const float ab  = (g == 2) ? -1.0f : 0.0f;

    float hxa[8];
#pragma unroll
    for (int h = 0; h < 8; h++) hxa[h] = 0.f;
    float cx = 0.f, hx = 0.f;

    const float* pb = g_pre + (size_t)b * 512 * 32 + lane;
    float* ob = out + (size_t)b * 512 * 8 + n;

    float p0 = __ldg(pb);
    float p1 = __ldg(pb + 32);
    for (int t = 0; t < 512; t++) {
        float p2 = __ldg(pb + ((t + 2) & 511) * 32);   // distance-2 prefetch

        // angle = pre + W_h . hx  (two parallel fma chains)
        float s1 = p0, s2 = 0.f;
        s1 = fmaf(wh[0], hxa[0], s1);  s2 = fmaf(wh[1], hxa[1], s2);
        s1 = fmaf(wh[2], hxa[2], s1);  s2 = fmaf(wh[3], hxa[3], s2);
        s1 = fmaf(wh[4], hxa[4], s1);  s2 = fmaf(wh[5], hxa[5], s2);
        s1 = fmaf(wh[6], hxa[6], s1);  s2 = fmaf(wh[7], hxa[7], s2);
        float ang = s1 + s2;

        float cm1 = __cosf(ang) - 1.0f;

        // Broadcast (cos-1) of this gate's 8 qubits; masked tree product.
        float vv[8];
#pragma unroll
        for (int j = 0; j < 8; j++) {
            float cj = __shfl_sync(FULL, cm1, segb + j);
            vv[j] = fmaf(incm[j], cj, 1.0f);   // include -> cos, exclude -> 1
        }
        float m = ((vv[0] * vv[1]) * (vv[2] * vv[3])) *
                  ((vv[4] * vv[5]) * (vv[6] * vv[7]));

        // a = am * sigmoid(scale*m) + ab   (ex2 + rcp, ~1e-6 accurate)
        float e = ex2_approx(m * sA2);
        float r = rcp_approx(1.0f + e);
        float a = fmaf(am, r, ab);

        // Gather the four gate activations for this lane's qubit.
        float fv = __shfl_sync(FULL, a, n);
        float iv = __shfl_sync(FULL, a, n + 8);
        float gv = __shfl_sync(FULL, a, n + 16);
        float ov = __shfl_sync(FULL, a, n + 24);

        cx = fmaf(fv, cx, iv * gv);

        // hx = ov * tanh(cx);  tanh(x) = 2*sigmoid(2x)-1
        float e2 = ex2_approx(cx * (-2.0f * L2E));
        float r2 = rcp_approx(1.0f + e2);
        hx = ov * fmaf(2.0f, r2, -1.0f);

        // Broadcast hx vector for next step's matvec.
#pragma unroll
        for (int h = 0; h < 8; h++) hxa[h] = __shfl_sync(FULL, hx, h);

        if (lane < 8) ob[t * 8] = hx;
        p0 = p1; p1 = p2;
    }

    if (lane < 8) {
        out[2097152 + b * 8 + n] = hx;           // final hx
        out[2097152 + 4096 + b * 8 + n] = cx;    // final cx
    }
}

// ---------------------------------------------------------------------------
extern "C" void kernel_launch(void* const* d_in, const int* in_sizes, int n_in,
                              void* d_out, int out_size) {
    const float* X  = (const float*)d_in[0];
    const float* Wf = (const float*)d_in[1];
    const float* bf = (const float*)d_in[2];
    const float* Wi = (const float*)d_in[3];
    const float* bi = (const float*)d_in[4];
    const float* Wg = (const float*)d_in[5];
    const float* bg = (const float*)d_in[6];
    const float* Wo = (const float*)d_in[7];
    const float* bo = (const float*)d_in[8];
    const float* th = (const float*)d_in[9];
    float* out = (float*)d_out;

    const int smem = SMEM_FLOATS * 4;   // 98432 B
    cudaFuncSetAttribute(gemm_kernel,
                         cudaFuncAttributeMaxDynamicSharedMemorySize, smem);

    gemm_kernel<<<512, 256, smem>>>(X, Wf, bf, Wi, bi, Wg, bg, Wo, bo, th);
    recur_kernel<<<128, 128>>>(Wf, Wi, Wg, Wo, out);
}